// round 12
// baseline (speedup 1.0000x reference)
#include <cuda_runtime.h>
#include <cstdint>

// ============================================================================
// StochasticLoop: x0 + sum_t uniform(sub_t)  until mean > 100, then *2.
// Exact JAX threefry2x32-20 reproduction (5 round-groups of 4 rounds, 6 key
// injections). Partitionable semantics (JAX default since 0.4.36):
//   split(k)  : child i = threefry_block(k, c0=0, c1=i), both output words.
//   bits(k,i) : out0 ^ out1 of threefry_block(k, c0=(i>>32)=0, c1=i).
//   uniform   : bitcast((bits>>9)|0x3F800000)-1  ==  float(bits>>9)*2^-23.
// Flip JAX_PARTITIONABLE to 0 for the legacy counter scheme (also 20-round).
//
// R11: byte-stable resubmission — R6..R10 never evaluated (GB300 broker
// container failures upstream of kernel execution). Logic identical to R6.
// ============================================================================

#define JAX_PARTITIONABLE 1

#define TMAX 204                      // trip count is ~199-200
#define N_ELEMS 20971520u             // 20*1024*1024
#define NQ (N_ELEMS / 4u)             // float4 quads
#define HALF_N (N_ELEMS / 2u)
#define THRESH_SUM 2097152000.0       // 100.0 * N_ELEMS  (mean > 100)

#define GRID_BLOCKS 1184
#define BLOCK_THREADS 256

__device__ double g_xsum[TMAX];       // sum of x after iteration t
__device__ uint2  g_subkeys[TMAX];    // per-iteration noise keys

// ---------------- threefry2x32-20 (5 groups of 4 rounds, 6 injections) ------

__device__ __forceinline__ void tf_round(uint32_t& x0, uint32_t& x1, int r) {
    x0 += x1;
    x1 = __funnelshift_l(x1, x1, r);  // rotl
    x1 ^= x0;
}

__device__ __forceinline__ void tf_block(uint32_t k0, uint32_t k1,
                                         uint32_t c0, uint32_t c1,
                                         uint32_t& o0, uint32_t& o1) {
    const uint32_t k2 = k0 ^ k1 ^ 0x1BD11BDAu;
    uint32_t x0 = c0 + k0, x1 = c1 + k1;
    // group 1 (rot set 0), inject ks[1], ks[2]+1
    tf_round(x0, x1, 13); tf_round(x0, x1, 15); tf_round(x0, x1, 26); tf_round(x0, x1, 6);
    x0 += k1; x1 += k2 + 1u;
    // group 2 (rot set 1), inject ks[2], ks[0]+2
    tf_round(x0, x1, 17); tf_round(x0, x1, 29); tf_round(x0, x1, 16); tf_round(x0, x1, 24);
    x0 += k2; x1 += k0 + 2u;
    // group 3 (rot set 0), inject ks[0], ks[1]+3
    tf_round(x0, x1, 13); tf_round(x0, x1, 15); tf_round(x0, x1, 26); tf_round(x0, x1, 6);
    x0 += k0; x1 += k1 + 3u;
    // group 4 (rot set 1), inject ks[1], ks[2]+4
    tf_round(x0, x1, 17); tf_round(x0, x1, 29); tf_round(x0, x1, 16); tf_round(x0, x1, 24);
    x0 += k1; x1 += k2 + 4u;
    // group 5 (rot set 0), inject ks[2], ks[0]+5
    tf_round(x0, x1, 13); tf_round(x0, x1, 15); tf_round(x0, x1, 26); tf_round(x0, x1, 6);
    x0 += k2; x1 += k0 + 5u;
    o0 = x0; o1 = x1;
}

// ---------------- init: zero sums, build key chain ----------------

__global__ void sl_init_kernel() {
    for (int i = threadIdx.x; i < TMAX; i += blockDim.x) g_xsum[i] = 0.0;
    if (threadIdx.x == 0) {
        uint32_t k0 = 0u, k1 = 42u;   // jax.random.key(42) -> (hi=0, lo=42)
        for (int t = 0; t < TMAX; ++t) {
            uint32_t n0, n1, s0, s1;
#if JAX_PARTITIONABLE
            // split(k,2): keys[0]=block(k,0,0), keys[1]=block(k,0,1)
            tf_block(k0, k1, 0u, 0u, n0, n1);
            tf_block(k0, k1, 0u, 1u, s0, s1);
#else
            // legacy split: counts [0,1,2,3] -> blocks (0,2) and (1,3);
            // result = concat(word0s, word1s).reshape(2,2):
            //   keys[0]=(y0_b0, y0_b1), keys[1]=(y1_b0, y1_b1)
            uint32_t a0, a1, b0, b1;
            tf_block(k0, k1, 0u, 2u, a0, a1);
            tf_block(k0, k1, 1u, 3u, b0, b1);
            n0 = a0; n1 = b0; s0 = a1; s1 = b1;
#endif
            g_subkeys[t] = make_uint2(s0, s1);
            k0 = n0; k1 = n1;
        }
    }
}

// ---------------- one loop iteration (noise add + global sum) ----------------

__global__ void __launch_bounds__(BLOCK_THREADS, 4)
sl_iter_kernel(float* __restrict__ out, const float* __restrict__ xin, int t) {
    if (t > 0) {
        const double prev = g_xsum[t - 1];
        if (prev > THRESH_SUM) {            // mean already > 100: loop halted
            if (threadIdx.x == 0) g_xsum[t] = prev;  // forward (same value from all blocks)
            return;
        }
    }
    const float* __restrict__ src = (t == 0) ? xin : out;
    const uint2 sk = g_subkeys[t];
    const uint32_t k0 = sk.x, k1 = sk.y;

    double sd = 0.0;
    const uint32_t stride = gridDim.x * blockDim.x;

#if JAX_PARTITIONABLE
    for (uint32_t q = blockIdx.x * blockDim.x + threadIdx.x; q < NQ; q += stride) {
        const uint32_t i = q * 4u;
        float4 v = *reinterpret_cast<const float4*>(src + i);
        uint32_t a0, a1, b0, b1, c0, c1, d0, d1;
        tf_block(k0, k1, 0u, i + 0u, a0, a1);
        tf_block(k0, k1, 0u, i + 1u, b0, b1);
        tf_block(k0, k1, 0u, i + 2u, c0, c1);
        tf_block(k0, k1, 0u, i + 3u, d0, d1);
        // x += u with u = m*2^-23 exact -> single-rounded FMA == FADD(x, u)
        v.x = fmaf((float)((a0 ^ a1) >> 9), 0x1p-23f, v.x);
        v.y = fmaf((float)((b0 ^ b1) >> 9), 0x1p-23f, v.y);
        v.z = fmaf((float)((c0 ^ c1) >> 9), 0x1p-23f, v.z);
        v.w = fmaf((float)((d0 ^ d1) >> 9), 0x1p-23f, v.w);
        *reinterpret_cast<float4*>(out + i) = v;
        sd += (double)((v.x + v.y) + (v.z + v.w));
    }
#else
    // legacy: block b in [0, N/2) consumes counters (b, b+N/2); word0 -> elem b,
    // word1 -> elem b+N/2. Process 4 blocks per thread-iter: float4 at [b]
    // (word0s) and float4 at [b+HALF_N] (word1s). One block serves 2 elements.
    const uint32_t NG = HALF_N / 4u;
    for (uint32_t q = blockIdx.x * blockDim.x + threadIdx.x; q < NG; q += stride) {
        const uint32_t b = q * 4u;
        float4 lo = *reinterpret_cast<const float4*>(src + b);
        float4 hi = *reinterpret_cast<const float4*>(src + b + HALF_N);
        uint32_t a0, a1, b0, b1, c0, c1, d0, d1;
        tf_block(k0, k1, b + 0u, b + 0u + HALF_N, a0, a1);
        tf_block(k0, k1, b + 1u, b + 1u + HALF_N, b0, b1);
        tf_block(k0, k1, b + 2u, b + 2u + HALF_N, c0, c1);
        tf_block(k0, k1, b + 3u, b + 3u + HALF_N, d0, d1);
        lo.x = fmaf((float)(a0 >> 9), 0x1p-23f, lo.x);
        lo.y = fmaf((float)(b0 >> 9), 0x1p-23f, lo.y);
        lo.z = fmaf((float)(c0 >> 9), 0x1p-23f, lo.z);
        lo.w = fmaf((float)(d0 >> 9), 0x1p-23f, lo.w);
        hi.x = fmaf((float)(a1 >> 9), 0x1p-23f, hi.x);
        hi.y = fmaf((float)(b1 >> 9), 0x1p-23f, hi.y);
        hi.z = fmaf((float)(c1 >> 9), 0x1p-23f, hi.z);
        hi.w = fmaf((float)(d1 >> 9), 0x1p-23f, hi.w);
        *reinterpret_cast<float4*>(out + b) = lo;
        *reinterpret_cast<float4*>(out + b + HALF_N) = hi;
        sd += (double)(((lo.x + lo.y) + (lo.z + lo.w))
                     + ((hi.x + hi.y) + (hi.z + hi.w)));
    }
#endif

    // block reduction (double) -> one atomicAdd per block
#pragma unroll
    for (int o = 16; o > 0; o >>= 1)
        sd += __shfl_xor_sync(0xffffffffu, sd, o);
    __shared__ double wsum[BLOCK_THREADS / 32];
    const int warp = threadIdx.x >> 5;
    if ((threadIdx.x & 31) == 0) wsum[warp] = sd;
    __syncthreads();
    if (threadIdx.x == 0) {
        double tot = 0.0;
#pragma unroll
        for (int w = 0; w < BLOCK_THREADS / 32; ++w) tot += wsum[w];
        atomicAdd(&g_xsum[t], tot);
    }
}

// ---------------- finalize: x * 2 ----------------

__global__ void __launch_bounds__(BLOCK_THREADS, 4)
sl_finalize_kernel(float* __restrict__ out) {
    const uint32_t stride = gridDim.x * blockDim.x;
    for (uint32_t q = blockIdx.x * blockDim.x + threadIdx.x; q < NQ; q += stride) {
        float4 v = *reinterpret_cast<float4*>(out + q * 4u);
        v.x *= 2.0f; v.y *= 2.0f; v.z *= 2.0f; v.w *= 2.0f;
        *reinterpret_cast<float4*>(out + q * 4u) = v;
    }
}

// ---------------- launch ----------------

extern "C" void kernel_launch(void* const* d_in, const int* in_sizes, int n_in,
                              void* d_out, int out_size) {
    const float* x = (const float*)d_in[0];
    float* out = (float*)d_out;

    sl_init_kernel<<<1, 256>>>();
    for (int t = 0; t < TMAX; ++t)
        sl_iter_kernel<<<GRID_BLOCKS, BLOCK_THREADS>>>(out, x, t);
    sl_finalize_kernel<<<GRID_BLOCKS, BLOCK_THREADS>>>(out);
}

// round 14
// speedup vs baseline: 1.6538x; 1.6538x over previous
#include <cuda_runtime.h>
#include <cstdint>

// ============================================================================
// StochasticLoop: x0 + sum_t uniform(sub_t)  until mean > 100, then *2.
// Exact JAX threefry2x32-20, partitionable semantics (adjudicated: rel_err=0).
//
// R13 perf: the R12 ncu showed alu=82.2% / fma=22.9% -> single-pipe bound.
// Rebalance: rotl(x,r) == lo|hi of (uint64)x * 2^r  -> IMAD.WIDE on the FMA
// pipe, and (lo|hi)^x0 fuses to ONE LOP3. Round cost goes ~2.5 alu + 0.5 fma
// -> ~1.5 alu + 1.5 fma. Also: (bits>>9) via wide-IMAD hi word, and the loop
// accumulator is fp32 (no in-loop DADD; decision margin ~1e6 >> error <1).
// ============================================================================

#define TMAX 204                      // trip count is ~199-200
#define N_ELEMS 20971520u             // 20*1024*1024
#define NQ (N_ELEMS / 4u)             // float4 quads
#define THRESH_SUM 2097152000.0       // 100.0 * N_ELEMS  (mean > 100)

#define GRID_BLOCKS 1184
#define BLOCK_THREADS 256

__device__ double g_xsum[TMAX];       // sum of x after iteration t
__device__ uint2  g_subkeys[TMAX];    // per-iteration noise keys

// ---------------- threefry2x32-20 helpers ----------------

// FMA-pipe rotate: rotl(x,r) = lo|hi of 64-bit product x * 2^r (IMAD.WIDE.U32)
__device__ __forceinline__ uint32_t rotl_m(uint32_t x, int r) {
    const uint64_t p = (uint64_t)x * ((uint64_t)(1u << r));
    return (uint32_t)p | (uint32_t)(p >> 32);
}

// round: x0+=x1; x1 = rotl(x1,r) ^ x0   — the (lo|hi)^x0 is one LOP3
__device__ __forceinline__ void tf_round_m(uint32_t& x0, uint32_t& x1, int r) {
    x0 += x1;
    x1 = rotl_m(x1, r) ^ x0;
}

// full 20-round block, IMAD-rotate version (hot path)
__device__ __forceinline__ void tf_block_m(uint32_t k0, uint32_t k1, uint32_t k2,
                                           uint32_t c1,
                                           uint32_t& o0, uint32_t& o1) {
    uint32_t x0 = k0, x1 = c1 + k1;          // c0 == 0 always in this problem
    tf_round_m(x0, x1, 13); tf_round_m(x0, x1, 15); tf_round_m(x0, x1, 26); tf_round_m(x0, x1, 6);
    x0 += k1; x1 += k2 + 1u;
    tf_round_m(x0, x1, 17); tf_round_m(x0, x1, 29); tf_round_m(x0, x1, 16); tf_round_m(x0, x1, 24);
    x0 += k2; x1 += k0 + 2u;
    tf_round_m(x0, x1, 13); tf_round_m(x0, x1, 15); tf_round_m(x0, x1, 26); tf_round_m(x0, x1, 6);
    x0 += k0; x1 += k1 + 3u;
    tf_round_m(x0, x1, 17); tf_round_m(x0, x1, 29); tf_round_m(x0, x1, 16); tf_round_m(x0, x1, 24);
    x0 += k1; x1 += k2 + 4u;
    tf_round_m(x0, x1, 13); tf_round_m(x0, x1, 15); tf_round_m(x0, x1, 26); tf_round_m(x0, x1, 6);
    x0 += k2; x1 += k0 + 5u;
    o0 = x0; o1 = x1;
}

// (o0^o1)>>9 as hi word of (o0^o1)*2^23  (shift moved to FMA pipe), then
// exact u = m * 2^-23, fused into the add:  x' = fma(m, 2^-23, x)
__device__ __forceinline__ float add_u01(float x, uint32_t o0, uint32_t o1) {
    const uint64_t p = (uint64_t)(o0 ^ o1) * ((uint64_t)(1u << 23));
    return fmaf((float)(uint32_t)(p >> 32), 0x1p-23f, x);
}

// ---------------- init: zero sums, build key chain (1 thread, cold) ---------

__device__ __forceinline__ void tf_block_ref(uint32_t k0, uint32_t k1,
                                             uint32_t c0, uint32_t c1,
                                             uint32_t& o0, uint32_t& o1) {
    const uint32_t k2 = k0 ^ k1 ^ 0x1BD11BDAu;
    uint32_t x0 = c0 + k0, x1 = c1 + k1;
#define TF_R(r) { x0 += x1; x1 = __funnelshift_l(x1, x1, r); x1 ^= x0; }
    TF_R(13) TF_R(15) TF_R(26) TF_R(6)   x0 += k1; x1 += k2 + 1u;
    TF_R(17) TF_R(29) TF_R(16) TF_R(24)  x0 += k2; x1 += k0 + 2u;
    TF_R(13) TF_R(15) TF_R(26) TF_R(6)   x0 += k0; x1 += k1 + 3u;
    TF_R(17) TF_R(29) TF_R(16) TF_R(24)  x0 += k1; x1 += k2 + 4u;
    TF_R(13) TF_R(15) TF_R(26) TF_R(6)   x0 += k2; x1 += k0 + 5u;
#undef TF_R
    o0 = x0; o1 = x1;
}

__global__ void sl_init_kernel() {
    for (int i = threadIdx.x; i < TMAX; i += blockDim.x) g_xsum[i] = 0.0;
    if (threadIdx.x == 0) {
        uint32_t k0 = 0u, k1 = 42u;   // jax.random.key(42) -> (hi=0, lo=42)
        for (int t = 0; t < TMAX; ++t) {
            // split(k,2): keys[0]=block(k,0,0) -> next key; keys[1]=block(k,0,1) -> subkey
            uint32_t n0, n1, s0, s1;
            tf_block_ref(k0, k1, 0u, 0u, n0, n1);
            tf_block_ref(k0, k1, 0u, 1u, s0, s1);
            g_subkeys[t] = make_uint2(s0, s1);
            k0 = n0; k1 = n1;
        }
    }
}

// ---------------- one loop iteration (noise add + global sum) ----------------

__global__ void __launch_bounds__(BLOCK_THREADS, 4)
sl_iter_kernel(float* __restrict__ out, const float* __restrict__ xin, int t) {
    if (t > 0) {
        const double prev = g_xsum[t - 1];
        if (prev > THRESH_SUM) {            // mean already > 100: loop halted
            if (threadIdx.x == 0) g_xsum[t] = prev;  // forward (same value from all blocks)
            return;
        }
    }
    const float* __restrict__ src = (t == 0) ? xin : out;
    const uint2 sk = g_subkeys[t];
    const uint32_t k0 = sk.x, k1 = sk.y;
    const uint32_t k2 = k0 ^ k1 ^ 0x1BD11BDAu;

    float s = 0.0f;                        // fp32 accumulation (see header note)
    const uint32_t stride = gridDim.x * blockDim.x;

    for (uint32_t q = blockIdx.x * blockDim.x + threadIdx.x; q < NQ; q += stride) {
        const uint32_t i = q * 4u;
        float4 v = *reinterpret_cast<const float4*>(src + i);
        uint32_t a0, a1, b0, b1, c0, c1, d0, d1;
        tf_block_m(k0, k1, k2, i + 0u, a0, a1);
        tf_block_m(k0, k1, k2, i + 1u, b0, b1);
        tf_block_m(k0, k1, k2, i + 2u, c0, c1);
        tf_block_m(k0, k1, k2, i + 3u, d0, d1);
        v.x = add_u01(v.x, a0, a1);
        v.y = add_u01(v.y, b0, b1);
        v.z = add_u01(v.z, c0, c1);
        v.w = add_u01(v.w, d0, d1);
        *reinterpret_cast<float4*>(out + i) = v;
        s += (v.x + v.y) + (v.z + v.w);
    }

    // block reduction (fp32) -> one double atomicAdd per block
#pragma unroll
    for (int o = 16; o > 0; o >>= 1)
        s += __shfl_xor_sync(0xffffffffu, s, o);
    __shared__ float wsum[BLOCK_THREADS / 32];
    const int warp = threadIdx.x >> 5;
    if ((threadIdx.x & 31) == 0) wsum[warp] = s;
    __syncthreads();
    if (threadIdx.x == 0) {
        float tot = 0.0f;
#pragma unroll
        for (int w = 0; w < BLOCK_THREADS / 32; ++w) tot += wsum[w];
        atomicAdd(&g_xsum[t], (double)tot);
    }
}

// ---------------- finalize: x * 2 ----------------

__global__ void __launch_bounds__(BLOCK_THREADS, 4)
sl_finalize_kernel(float* __restrict__ out) {
    const uint32_t stride = gridDim.x * blockDim.x;
    for (uint32_t q = blockIdx.x * blockDim.x + threadIdx.x; q < NQ; q += stride) {
        float4 v = *reinterpret_cast<float4*>(out + q * 4u);
        v.x *= 2.0f; v.y *= 2.0f; v.z *= 2.0f; v.w *= 2.0f;
        *reinterpret_cast<float4*>(out + q * 4u) = v;
    }
}

// ---------------- launch ----------------

extern "C" void kernel_launch(void* const* d_in, const int* in_sizes, int n_in,
                              void* d_out, int out_size) {
    const float* x = (const float*)d_in[0];
    float* out = (float*)d_out;

    sl_init_kernel<<<1, 256>>>();
    for (int t = 0; t < TMAX; ++t)
        sl_iter_kernel<<<GRID_BLOCKS, BLOCK_THREADS>>>(out, x, t);
    sl_finalize_kernel<<<GRID_BLOCKS, BLOCK_THREADS>>>(out);
}